// round 1
// baseline (speedup 1.0000x reference)
#include <cuda_runtime.h>

#define NN 100000
#define DIM 64
#define NREL 16
#define EPB 2048      // edges bucketed per block
#define TILE_E 128    // edge rows per GEMM tile

__device__ float g_neighbor[NN * DIM];

// ---------- f32x2 helpers (Blackwell FFMA2 via PTX) ----------
__device__ __forceinline__ unsigned long long pack2(float x, float y) {
    unsigned long long r;
    asm("mov.b64 %0, {%1, %2};" : "=l"(r) : "f"(x), "f"(y));
    return r;
}
__device__ __forceinline__ void fma2(unsigned long long& d, unsigned long long a, unsigned long long b) {
    asm("fma.rn.f32x2 %0, %1, %2, %0;" : "+l"(d) : "l"(a), "l"(b));
}
__device__ __forceinline__ float2 unpack2(unsigned long long v) {
    float2 r;
    r.x = __uint_as_float((unsigned)(v & 0xffffffffull));
    r.y = __uint_as_float((unsigned)(v >> 32));
    return r;
}
__device__ __forceinline__ float fast_tanh(float x) {
    // tanh(x) = 1 - 2/(exp(2x)+1); __expf = MUFU.EX2 path, ~1e-7 rel; saturates correctly.
    float e = __expf(2.0f * x);
    return 1.0f - __fdividef(2.0f, e + 1.0f);
}
__device__ __forceinline__ void red_add_v4(float* addr, float a, float b, float c, float d) {
    asm volatile("red.global.add.v4.f32 [%0], {%1, %2, %3, %4};"
                 :: "l"(addr), "f"(a), "f"(b), "f"(c), "f"(d) : "memory");
}

// ---------- kernel 1: zero the neighbor accumulator ----------
__global__ void zero_kernel(int n4) {
    int i = blockIdx.x * blockDim.x + threadIdx.x;
    if (i < n4) ((float4*)g_neighbor)[i] = make_float4(0.f, 0.f, 0.f, 0.f);
}

// ---------- kernel 2: per-edge transform + attention + scatter ----------
// Block: 128 threads. Buckets its 2048 edges by relation in smem, then for each
// relation keeps W_R[r] in smem and runs register-tiled 128x64x64 GEMM chunks
// (8 rows x 8 cols per thread, f32x2 accumulators), computes att per edge, and
// red.v4-scatters att * x_src into g_neighbor[dst].
__global__ __launch_bounds__(128, 1) void edge_kernel(
    const float* __restrict__ entity, const float* __restrict__ rel,
    const float* __restrict__ W_R,
    const int* __restrict__ src, const int* __restrict__ dst,
    const int* __restrict__ etype, int E)
{
    extern __shared__ float smem[];
    float* sW    = smem;                 // 64*64 = 4096 floats
    float* sX    = sW + 4096;            // transposed X: [k=64][row pad 132] = 8448
    float* sRe   = sX + 64 * 132;        // 64
    float* sAttP = sRe + 64;             // [128][9] = 1152 (pad 9 vs bank conflicts)
    int*   sIds  = (int*)(sAttP + 128 * 9);  // 2048
    int*   sCnt  = sIds + EPB;           // 16
    int*   sOff  = sCnt + NREL;          // 17
    int*   sCur  = sOff + NREL + 1;      // 16

    const int tid = threadIdx.x;
    const int e0  = blockIdx.x * EPB;

    // ---- local bucketing by relation ----
    if (tid < NREL) sCnt[tid] = 0;
    __syncthreads();
    for (int i = tid; i < EPB; i += 128) {
        int e = e0 + i;
        if (e < E) atomicAdd(&sCnt[etype[e]], 1);
    }
    __syncthreads();
    if (tid == 0) {
        int acc = 0;
        for (int r = 0; r < NREL; r++) { sOff[r] = acc; acc += sCnt[r]; }
        sOff[NREL] = acc;
    }
    __syncthreads();
    if (tid < NREL) sCur[tid] = sOff[tid];
    __syncthreads();
    for (int i = tid; i < EPB; i += 128) {
        int e = e0 + i;
        if (e < E) {
            int pos = atomicAdd(&sCur[etype[e]], 1);
            sIds[pos] = e;
        }
    }
    // sync at top of relation loop covers the scatter pass

    const int ti = tid & 15;   // row-group 0..15 (rows ti*8 .. ti*8+7)
    const int tj = tid >> 4;   // col-group 0..7  (cols tj*8 .. tj*8+7)

    for (int r = 0; r < NREL; r++) {
        __syncthreads();
        // load W_R[r] (row-major [d][e], exactly the GEMM B layout) and rel row
        {
            const float4* wr4 = (const float4*)(W_R + (size_t)r * 64 * 64);
            for (int i = tid; i < 1024; i += 128) ((float4*)sW)[i] = wr4[i];
            if (tid < 16) ((float4*)sRe)[tid] = ((const float4*)(rel + r * 64))[tid];
        }
        int b0    = sOff[r];
        int cnt_r = sOff[r + 1] - b0;

        for (int cb = 0; cb < cnt_r; cb += TILE_E) {
            int cnt = min(TILE_E, cnt_r - cb);
            __syncthreads();   // previous tile done with sX/sAttP; W/Re visible
            // ---- gather X (transposed) ----
            if (tid < cnt) {
                int eid = sIds[b0 + cb + tid];
                const float4* xp = (const float4*)(entity + (size_t)src[eid] * DIM);
                #pragma unroll
                for (int q = 0; q < 16; q++) {
                    float4 v = xp[q];
                    sX[(4 * q + 0) * 132 + tid] = v.x;
                    sX[(4 * q + 1) * 132 + tid] = v.y;
                    sX[(4 * q + 2) * 132 + tid] = v.z;
                    sX[(4 * q + 3) * 132 + tid] = v.w;
                }
            }
            __syncthreads();

            // ---- 128x64x64 GEMM, f32x2, 8x8 per thread ----
            unsigned long long acc[4][8];
            #pragma unroll
            for (int p = 0; p < 4; p++)
                #pragma unroll
                for (int c = 0; c < 8; c++) acc[p][c] = 0ull;

            const float* xb = sX + ti * 8;
            const float* wb = sW + tj * 8;
            #pragma unroll 8
            for (int k = 0; k < 64; k++) {
                float4 a0 = *(const float4*)(xb + k * 132);
                float4 a1 = *(const float4*)(xb + k * 132 + 4);
                float4 w0 = *(const float4*)(wb + k * 64);
                float4 w1 = *(const float4*)(wb + k * 64 + 4);
                unsigned long long A[4] = { pack2(a0.x, a0.y), pack2(a0.z, a0.w),
                                            pack2(a1.x, a1.y), pack2(a1.z, a1.w) };
                unsigned long long B[8] = { pack2(w0.x, w0.x), pack2(w0.y, w0.y),
                                            pack2(w0.z, w0.z), pack2(w0.w, w0.w),
                                            pack2(w1.x, w1.x), pack2(w1.y, w1.y),
                                            pack2(w1.z, w1.z), pack2(w1.w, w1.w) };
                #pragma unroll
                for (int p = 0; p < 4; p++)
                    #pragma unroll
                    for (int c = 0; c < 8; c++) fma2(acc[p][c], A[p], B[c]);
            }

            // ---- attention partials: part[row] = sum_c m*tanh(m + re_c) ----
            float rec[8];
            #pragma unroll
            for (int c = 0; c < 8; c++) rec[c] = sRe[tj * 8 + c];
            float part[8];
            #pragma unroll
            for (int i = 0; i < 8; i++) part[i] = 0.f;
            #pragma unroll
            for (int p = 0; p < 4; p++) {
                #pragma unroll
                for (int c = 0; c < 8; c++) {
                    float2 m = unpack2(acc[p][c]);
                    part[2 * p + 0] += m.x * fast_tanh(m.x + rec[c]);
                    part[2 * p + 1] += m.y * fast_tanh(m.y + rec[c]);
                }
            }
            #pragma unroll
            for (int i = 0; i < 8; i++) sAttP[(ti * 8 + i) * 9 + tj] = part[i];
            __syncthreads();

            // ---- reduce att + scatter msg = att * x_src into g_neighbor[dst] ----
            if (tid < cnt) {
                float att = 0.f;
                #pragma unroll
                for (int c = 0; c < 8; c++) att += sAttP[tid * 9 + c];
                int eid = sIds[b0 + cb + tid];
                int s = src[eid];
                int d = dst[eid];
                const float4* xp = (const float4*)(entity + (size_t)s * DIM);
                float* np = g_neighbor + (size_t)d * DIM;
                #pragma unroll
                for (int q = 0; q < 16; q++) {
                    float4 v = xp[q];
                    red_add_v4(np + 4 * q, att * v.x, att * v.y, att * v.z, att * v.w);
                }
            }
        }
    }
}

// ---------- kernel 3: combine out = leaky_relu([h;nb] @ W_w^T + b) + h ----------
__global__ __launch_bounds__(128, 1) void combine_kernel(
    const float* __restrict__ entity, const float* __restrict__ W_w,
    const float* __restrict__ W_b, float* __restrict__ out, int n_nodes)
{
    extern __shared__ float smem[];
    float* sW = smem;                  // transposed W: [k=128][j=64] = 8192
    float* sX = sW + 8192;             // transposed X: [k=128][row pad 132] = 16896
    float* sB = sX + 128 * 132;        // 64

    const int tid = threadIdx.x;
    const int n0  = blockIdx.x * 128;

    // W_w is [64][128]; we want sW[k*64 + j] = W_w[j*128 + k]
    for (int i = tid; i < 8192; i += 128) {
        int j = i >> 7, k = i & 127;
        sW[k * 64 + j] = W_w[i];
    }
    if (tid < 64) sB[tid] = W_b[tid];

    {
        int n = n0 + tid;
        if (n < n_nodes) {
            const float4* hp = (const float4*)(entity + (size_t)n * DIM);
            const float4* np = (const float4*)(g_neighbor + (size_t)n * DIM);
            #pragma unroll
            for (int q = 0; q < 16; q++) {
                float4 v = hp[q];
                sX[(4 * q + 0) * 132 + tid] = v.x;
                sX[(4 * q + 1) * 132 + tid] = v.y;
                sX[(4 * q + 2) * 132 + tid] = v.z;
                sX[(4 * q + 3) * 132 + tid] = v.w;
                float4 w = np[q];
                sX[(64 + 4 * q + 0) * 132 + tid] = w.x;
                sX[(64 + 4 * q + 1) * 132 + tid] = w.y;
                sX[(64 + 4 * q + 2) * 132 + tid] = w.z;
                sX[(64 + 4 * q + 3) * 132 + tid] = w.w;
            }
        }
    }
    __syncthreads();

    const int ti = tid & 15;
    const int tj = tid >> 4;

    unsigned long long acc[4][8];
    #pragma unroll
    for (int p = 0; p < 4; p++)
        #pragma unroll
        for (int c = 0; c < 8; c++) acc[p][c] = 0ull;

    const float* xb = sX + ti * 8;
    const float* wb = sW + tj * 8;
    #pragma unroll 8
    for (int k = 0; k < 128; k++) {
        float4 a0 = *(const float4*)(xb + k * 132);
        float4 a1 = *(const float4*)(xb + k * 132 + 4);
        float4 w0 = *(const float4*)(wb + k * 64);
        float4 w1 = *(const float4*)(wb + k * 64 + 4);
        unsigned long long A[4] = { pack2(a0.x, a0.y), pack2(a0.z, a0.w),
                                    pack2(a1.x, a1.y), pack2(a1.z, a1.w) };
        unsigned long long B[8] = { pack2(w0.x, w0.x), pack2(w0.y, w0.y),
                                    pack2(w0.z, w0.z), pack2(w0.w, w0.w),
                                    pack2(w1.x, w1.x), pack2(w1.y, w1.y),
                                    pack2(w1.z, w1.z), pack2(w1.w, w1.w) };
        #pragma unroll
        for (int p = 0; p < 4; p++)
            #pragma unroll
            for (int c = 0; c < 8; c++) fma2(acc[p][c], A[p], B[c]);
    }

    float bcol[8];
    #pragma unroll
    for (int c = 0; c < 8; c++) bcol[c] = sB[tj * 8 + c];

    #pragma unroll
    for (int p = 0; p < 4; p++) {
        int r0 = n0 + ti * 8 + 2 * p;      // first row of this pair
        float v0[8], v1[8];
        #pragma unroll
        for (int c = 0; c < 8; c++) {
            float2 m = unpack2(acc[p][c]);
            float x0 = m.x + bcol[c];
            float x1 = m.y + bcol[c];
            v0[c] = (x0 > 0.f) ? x0 : 0.01f * x0;
            v1[c] = (x1 > 0.f) ? x1 : 0.01f * x1;
        }
        if (r0 < n_nodes) {
            const float4* hp = (const float4*)(entity + (size_t)r0 * DIM);
            float4 e0 = hp[tj * 2], e1 = hp[tj * 2 + 1];
            float4* op = (float4*)(out + (size_t)r0 * DIM + tj * 8);
            op[0] = make_float4(v0[0] + e0.x, v0[1] + e0.y, v0[2] + e0.z, v0[3] + e0.w);
            op[1] = make_float4(v0[4] + e1.x, v0[5] + e1.y, v0[6] + e1.z, v0[7] + e1.w);
        }
        if (r0 + 1 < n_nodes) {
            const float4* hp = (const float4*)(entity + (size_t)(r0 + 1) * DIM);
            float4 e0 = hp[tj * 2], e1 = hp[tj * 2 + 1];
            float4* op = (float4*)(out + (size_t)(r0 + 1) * DIM + tj * 8);
            op[0] = make_float4(v1[0] + e0.x, v1[1] + e0.y, v1[2] + e0.z, v1[3] + e0.w);
            op[1] = make_float4(v1[4] + e1.x, v1[5] + e1.y, v1[6] + e1.z, v1[7] + e1.w);
        }
    }
}

extern "C" void kernel_launch(void* const* d_in, const int* in_sizes, int n_in,
                              void* d_out, int out_size)
{
    const float* entity = (const float*)d_in[0];
    const float* rel    = (const float*)d_in[1];
    const float* W_R    = (const float*)d_in[2];
    const float* W_w    = (const float*)d_in[3];
    const float* W_b    = (const float*)d_in[4];
    const int*   src    = (const int*)d_in[5];
    const int*   dst    = (const int*)d_in[6];
    const int*   etype  = (const int*)d_in[7];

    const int E = in_sizes[5];
    const int n = in_sizes[0] / DIM;

    const size_t smem_edge = (4096 + 64 * 132 + 64 + 128 * 9) * sizeof(float)
                             + (EPB + NREL + NREL + 1 + NREL) * sizeof(int);
    const size_t smem_comb = (8192 + 128 * 132 + 64) * sizeof(float);

    cudaFuncSetAttribute(edge_kernel, cudaFuncAttributeMaxDynamicSharedMemorySize, (int)smem_edge);
    cudaFuncSetAttribute(combine_kernel, cudaFuncAttributeMaxDynamicSharedMemorySize, (int)smem_comb);

    int n4 = n * DIM / 4;
    zero_kernel<<<(n4 + 255) / 256, 256>>>(n4);
    edge_kernel<<<(E + EPB - 1) / EPB, 128, smem_edge>>>(entity, rel, W_R, src, dst, etype, E);
    combine_kernel<<<(n + 127) / 128, 128, smem_comb>>>(entity, W_w, W_b, (float*)d_out, n);
}

// round 2
// speedup vs baseline: 1.4398x; 1.4398x over previous
#include <cuda_runtime.h>

#define NN 100000
#define DIM 64
#define NREL 16
#define EMAX 1000000
#define IDS_CAP (EMAX + NREL * 128)   // 1,002,048 (div by 4)

__device__ float g_neighbor[NN * DIM];
__device__ int   g_ids[IDS_CAP];
__device__ int   g_cnt[NREL];
__device__ int   g_off[NREL + 1];
__device__ int   g_cursor[NREL];

// ---------- f32x2 helpers ----------
__device__ __forceinline__ void fma2(unsigned long long& d, unsigned long long a, unsigned long long b) {
    asm("fma.rn.f32x2 %0, %1, %2, %0;" : "+l"(d) : "l"(a), "l"(b));
}
__device__ __forceinline__ float2 unpack2(unsigned long long v) {
    float2 r;
    r.x = __uint_as_float((unsigned)(v & 0xffffffffull));
    r.y = __uint_as_float((unsigned)(v >> 32));
    return r;
}
__device__ __forceinline__ unsigned long long pack2(float x, float y) {
    unsigned long long r;
    asm("mov.b64 %0, {%1, %2};" : "=l"(r) : "f"(x), "f"(y));
    return r;
}
__device__ __forceinline__ float fast_tanh(float x) {
    float e = __expf(2.0f * x);
    return 1.0f - __fdividef(2.0f, e + 1.0f);
}
__device__ __forceinline__ void red_add_v4(float* addr, float a, float b, float c, float d) {
    asm volatile("red.global.add.v4.f32 [%0], {%1, %2, %3, %4};"
                 :: "l"(addr), "f"(a), "f"(b), "f"(c), "f"(d) : "memory");
}

// ---------- init: zero neighbor, fill ids with -1, zero counters ----------
__global__ void init_kernel(int n4neigh, int n4ids) {
    int i = blockIdx.x * blockDim.x + threadIdx.x;
    if (i < n4neigh) ((float4*)g_neighbor)[i] = make_float4(0.f, 0.f, 0.f, 0.f);
    if (i < n4ids)   ((int4*)g_ids)[i] = make_int4(-1, -1, -1, -1);
    if (i < NREL)    g_cnt[i] = 0;
}

// ---------- histogram over etype ----------
__global__ void hist_kernel(const int* __restrict__ etype, int E) {
    __shared__ int h[NREL];
    if (threadIdx.x < NREL) h[threadIdx.x] = 0;
    __syncthreads();
    int stride = gridDim.x * blockDim.x;
    for (int i = blockIdx.x * blockDim.x + threadIdx.x; i < E; i += stride)
        atomicAdd(&h[etype[i]], 1);
    __syncthreads();
    if (threadIdx.x < NREL) atomicAdd(&g_cnt[threadIdx.x], h[threadIdx.x]);
}

// ---------- 128-aligned prefix ----------
__global__ void prefix_kernel() {
    if (threadIdx.x == 0) {
        int acc = 0;
        for (int r = 0; r < NREL; r++) {
            g_off[r] = acc;
            g_cursor[r] = acc;
            acc += (g_cnt[r] + 127) & ~127;
        }
        g_off[NREL] = acc;
    }
}

// ---------- scatter edge ids into relation-sorted array ----------
__global__ __launch_bounds__(256) void scatter_kernel(const int* __restrict__ etype, int E) {
    __shared__ int cnt[NREL], base[NREL];
    const int CH = 4096;
    int e0 = blockIdx.x * CH;
    if (threadIdx.x < NREL) cnt[threadIdx.x] = 0;
    __syncthreads();
    for (int i = threadIdx.x; i < CH; i += 256) {
        int e = e0 + i;
        if (e < E) atomicAdd(&cnt[etype[e]], 1);
    }
    __syncthreads();
    if (threadIdx.x < NREL) {
        base[threadIdx.x] = atomicAdd(&g_cursor[threadIdx.x], cnt[threadIdx.x]);
        cnt[threadIdx.x] = 0;
    }
    __syncthreads();
    for (int i = threadIdx.x; i < CH; i += 256) {
        int e = e0 + i;
        if (e < E) {
            int r = etype[e];
            int p = base[r] + atomicAdd(&cnt[r], 1);
            g_ids[p] = e;
        }
    }
}

// ---------- edge GEMM + attention + scatter (one relation per block) ----------
// 128 threads, tile = 128 edges x 64 cols, 8x8 per thread, f32x2 accumulators.
// W stored lane-duplicated in smem so B pairs come straight from LDS.128.
__global__ __launch_bounds__(128, 1) void edge_kernel(
    const float* __restrict__ entity, const float* __restrict__ rel,
    const float* __restrict__ W_R,
    const int* __restrict__ src, const int* __restrict__ dst)
{
    extern __shared__ float sm[];
    float* sW2   = sm;                 // 64 x 128 duplicated W (8192)
    float* sX    = sW2 + 8192;         // transposed X [k=64][row=128] (8192)
    float* sRe   = sX + 8192;          // 64
    float* sAttP = sRe + 64;           // [128][9] = 1152
    int*   sOff  = (int*)(sAttP + 1152); // 17
    int*   sIds  = sOff + 18;          // 128

    const int tid = threadIdx.x;
    if (tid < NREL + 1) sOff[tid] = g_off[tid];
    __syncthreads();

    const int p0 = blockIdx.x * 128;
    if (p0 >= sOff[NREL]) return;
    int r = 0;
    while (p0 >= sOff[r + 1]) r++;

    // load W_R[r] duplicated: sW2[k*128 + 2c] = sW2[k*128 + 2c+1] = W[k][c]
    {
        const float4* wr4 = (const float4*)(W_R + (size_t)r * 4096);
        for (int i = tid; i < 1024; i += 128) {
            float4 w = wr4[i];
            int k  = i >> 4;
            int c4 = i & 15;
            float* b = sW2 + k * 128 + c4 * 8;
            *(float4*)(b)     = make_float4(w.x, w.x, w.y, w.y);
            *(float4*)(b + 4) = make_float4(w.z, w.z, w.w, w.w);
        }
        if (tid < 16) ((float4*)sRe)[tid] = ((const float4*)(rel + r * 64))[tid];
    }

    // gather 128 edges (transposed into sX)
    const int id = g_ids[p0 + tid];
    sIds[tid] = id;
    if (id >= 0) {
        const float4* xp = (const float4*)(entity + (size_t)src[id] * DIM);
        #pragma unroll
        for (int q = 0; q < 16; q++) {
            float4 v = xp[q];
            sX[(4 * q + 0) * 128 + tid] = v.x;
            sX[(4 * q + 1) * 128 + tid] = v.y;
            sX[(4 * q + 2) * 128 + tid] = v.z;
            sX[(4 * q + 3) * 128 + tid] = v.w;
        }
    } else {
        #pragma unroll
        for (int k = 0; k < 64; k++) sX[k * 128 + tid] = 0.f;
    }
    __syncthreads();

    // ---- GEMM: rows paired in accumulator lanes, B pairs direct from smem ----
    const int ti = tid & 15;   // rows ti*8 .. ti*8+7
    const int tj = tid >> 4;   // cols tj*8 .. tj*8+7
    unsigned long long acc[4][8];
    #pragma unroll
    for (int p = 0; p < 4; p++)
        #pragma unroll
        for (int c = 0; c < 8; c++) acc[p][c] = 0ull;

    const float* xb = sX  + ti * 8;
    const float* wb = sW2 + tj * 16;
    #pragma unroll 8
    for (int k = 0; k < 64; k++) {
        ulonglong2 a01 = *(const ulonglong2*)(xb + k * 128);      // rows 0-3 as 2 pairs
        ulonglong2 a23 = *(const ulonglong2*)(xb + k * 128 + 4);  // rows 4-7
        ulonglong2 b0  = *(const ulonglong2*)(wb + k * 128);      // cols 0,1 dup-pairs
        ulonglong2 b1  = *(const ulonglong2*)(wb + k * 128 + 4);
        ulonglong2 b2  = *(const ulonglong2*)(wb + k * 128 + 8);
        ulonglong2 b3  = *(const ulonglong2*)(wb + k * 128 + 12);
        unsigned long long A[4] = { a01.x, a01.y, a23.x, a23.y };
        unsigned long long B[8] = { b0.x, b0.y, b1.x, b1.y, b2.x, b2.y, b3.x, b3.y };
        #pragma unroll
        for (int p = 0; p < 4; p++)
            #pragma unroll
            for (int c = 0; c < 8; c++) fma2(acc[p][c], A[p], B[c]);
    }

    // ---- attention partials ----
    float rec[8];
    #pragma unroll
    for (int c = 0; c < 8; c++) rec[c] = sRe[tj * 8 + c];
    float part[8];
    #pragma unroll
    for (int i = 0; i < 8; i++) part[i] = 0.f;
    #pragma unroll
    for (int p = 0; p < 4; p++) {
        #pragma unroll
        for (int c = 0; c < 8; c++) {
            float2 m = unpack2(acc[p][c]);
            part[2 * p + 0] += m.x * fast_tanh(m.x + rec[c]);
            part[2 * p + 1] += m.y * fast_tanh(m.y + rec[c]);
        }
    }
    #pragma unroll
    for (int i = 0; i < 8; i++) sAttP[(ti * 8 + i) * 9 + tj] = part[i];
    __syncthreads();

    // ---- reduce att, scatter att * x_src into g_neighbor[dst] ----
    if (id >= 0) {
        float att = 0.f;
        #pragma unroll
        for (int c = 0; c < 8; c++) att += sAttP[tid * 9 + c];
        const float4* xp = (const float4*)(entity + (size_t)src[id] * DIM);
        float* np = g_neighbor + (size_t)dst[id] * DIM;
        #pragma unroll
        for (int q = 0; q < 16; q++) {
            float4 v = xp[q];
            red_add_v4(np + 4 * q, att * v.x, att * v.y, att * v.z, att * v.w);
        }
    }
}

// ---------- combine: out = leaky_relu([h;nb] @ W_w^T + b) + h ----------
__global__ __launch_bounds__(128, 1) void combine_kernel(
    const float* __restrict__ entity, const float* __restrict__ W_w,
    const float* __restrict__ W_b, float* __restrict__ out, int n_nodes)
{
    extern __shared__ float smem[];
    float* sW = smem;                  // transposed W: [k=128][j=64] = 8192
    float* sX = sW + 8192;             // transposed X: [k=128][row pad 132] = 16896
    float* sB = sX + 128 * 132;        // 64

    const int tid = threadIdx.x;
    const int n0  = blockIdx.x * 128;

    for (int i = tid; i < 8192; i += 128) {
        int j = i >> 7, k = i & 127;
        sW[k * 64 + j] = W_w[i];
    }
    if (tid < 64) sB[tid] = W_b[tid];

    {
        int n = n0 + tid;
        if (n < n_nodes) {
            const float4* hp = (const float4*)(entity + (size_t)n * DIM);
            const float4* np = (const float4*)(g_neighbor + (size_t)n * DIM);
            #pragma unroll
            for (int q = 0; q < 16; q++) {
                float4 v = hp[q];
                sX[(4 * q + 0) * 132 + tid] = v.x;
                sX[(4 * q + 1) * 132 + tid] = v.y;
                sX[(4 * q + 2) * 132 + tid] = v.z;
                sX[(4 * q + 3) * 132 + tid] = v.w;
                float4 w = np[q];
                sX[(64 + 4 * q + 0) * 132 + tid] = w.x;
                sX[(64 + 4 * q + 1) * 132 + tid] = w.y;
                sX[(64 + 4 * q + 2) * 132 + tid] = w.z;
                sX[(64 + 4 * q + 3) * 132 + tid] = w.w;
            }
        }
    }
    __syncthreads();

    const int ti = tid & 15;
    const int tj = tid >> 4;

    unsigned long long acc[4][8];
    #pragma unroll
    for (int p = 0; p < 4; p++)
        #pragma unroll
        for (int c = 0; c < 8; c++) acc[p][c] = 0ull;

    const float* xb = sX + ti * 8;
    const float* wb = sW + tj * 8;
    #pragma unroll 8
    for (int k = 0; k < 128; k++) {
        float4 a0 = *(const float4*)(xb + k * 132);
        float4 a1 = *(const float4*)(xb + k * 132 + 4);
        float4 w0 = *(const float4*)(wb + k * 64);
        float4 w1 = *(const float4*)(wb + k * 64 + 4);
        unsigned long long A[4] = { pack2(a0.x, a0.y), pack2(a0.z, a0.w),
                                    pack2(a1.x, a1.y), pack2(a1.z, a1.w) };
        unsigned long long B[8] = { pack2(w0.x, w0.x), pack2(w0.y, w0.y),
                                    pack2(w0.z, w0.z), pack2(w0.w, w0.w),
                                    pack2(w1.x, w1.x), pack2(w1.y, w1.y),
                                    pack2(w1.z, w1.z), pack2(w1.w, w1.w) };
        #pragma unroll
        for (int p = 0; p < 4; p++)
            #pragma unroll
            for (int c = 0; c < 8; c++) fma2(acc[p][c], A[p], B[c]);
    }

    float bcol[8];
    #pragma unroll
    for (int c = 0; c < 8; c++) bcol[c] = sB[tj * 8 + c];

    #pragma unroll
    for (int p = 0; p < 4; p++) {
        int r0 = n0 + ti * 8 + 2 * p;
        float v0[8], v1[8];
        #pragma unroll
        for (int c = 0; c < 8; c++) {
            float2 m = unpack2(acc[p][c]);
            float x0 = m.x + bcol[c];
            float x1 = m.y + bcol[c];
            v0[c] = (x0 > 0.f) ? x0 : 0.01f * x0;
            v1[c] = (x1 > 0.f) ? x1 : 0.01f * x1;
        }
        if (r0 < n_nodes) {
            const float4* hp = (const float4*)(entity + (size_t)r0 * DIM);
            float4 e0 = hp[tj * 2], e1 = hp[tj * 2 + 1];
            float4* op = (float4*)(out + (size_t)r0 * DIM + tj * 8);
            op[0] = make_float4(v0[0] + e0.x, v0[1] + e0.y, v0[2] + e0.z, v0[3] + e0.w);
            op[1] = make_float4(v0[4] + e1.x, v0[5] + e1.y, v0[6] + e1.z, v0[7] + e1.w);
        }
        if (r0 + 1 < n_nodes) {
            const float4* hp = (const float4*)(entity + (size_t)(r0 + 1) * DIM);
            float4 e0 = hp[tj * 2], e1 = hp[tj * 2 + 1];
            float4* op = (float4*)(out + (size_t)(r0 + 1) * DIM + tj * 8);
            op[0] = make_float4(v1[0] + e0.x, v1[1] + e0.y, v1[2] + e0.z, v1[3] + e0.w);
            op[1] = make_float4(v1[4] + e1.x, v1[5] + e1.y, v1[6] + e1.z, v1[7] + e1.w);
        }
    }
}

extern "C" void kernel_launch(void* const* d_in, const int* in_sizes, int n_in,
                              void* d_out, int out_size)
{
    const float* entity = (const float*)d_in[0];
    const float* rel    = (const float*)d_in[1];
    const float* W_R    = (const float*)d_in[2];
    const float* W_w    = (const float*)d_in[3];
    const float* W_b    = (const float*)d_in[4];
    const int*   src    = (const int*)d_in[5];
    const int*   dst    = (const int*)d_in[6];
    const int*   etype  = (const int*)d_in[7];

    const int E = in_sizes[5];
    const int n = in_sizes[0] / DIM;

    const size_t smem_edge = (8192 + 8192 + 64 + 1152) * sizeof(float) + (18 + 128) * sizeof(int);
    const size_t smem_comb = (8192 + 128 * 132 + 64) * sizeof(float);
    cudaFuncSetAttribute(edge_kernel, cudaFuncAttributeMaxDynamicSharedMemorySize, (int)smem_edge);
    cudaFuncSetAttribute(combine_kernel, cudaFuncAttributeMaxDynamicSharedMemorySize, (int)smem_comb);

    int n4neigh = n * DIM / 4;
    int n4ids   = IDS_CAP / 4;
    int initmax = n4neigh > n4ids ? n4neigh : n4ids;
    init_kernel<<<(initmax + 255) / 256, 256>>>(n4neigh, n4ids);
    hist_kernel<<<512, 256>>>(etype, E);
    prefix_kernel<<<1, 32>>>();
    scatter_kernel<<<(E + 4095) / 4096, 256>>>(etype, E);

    int tiles = E / 128 + NREL + 1;
    edge_kernel<<<tiles, 128, smem_edge>>>(entity, rel, W_R, src, dst);
    combine_kernel<<<(n + 127) / 128, 128, smem_comb>>>(entity, W_w, W_b, (float*)d_out, n);
}